// round 3
// baseline (speedup 1.0000x reference)
#include <cuda_runtime.h>
#include <math.h>

#define D_MODEL 2048
#define NEXP    128
#define BM      64
#define BK      16
#define NTHREADS 256
#define TOPK    8

#define ADUP_W  (2*BM + 4)    // 132, pad keeps 16B alignment + fewer store conflicts
#define BS_W    (NEXP + 4)    // 132

struct SmemT {
    union {
        struct {
            float As[2][BK][ADUP_W];  // x tile, transposed + token-duplicated: As[buf][k][2m]==As[..][2m+1]==x[m][k]
            float Bs[2][BK][BS_W];    // w tile, transposed: Bs[buf][k][e]
        } g;
        float Ls[BM][NEXP];           // logits tile for epilogue
    };
};

__device__ __forceinline__ unsigned long long ffma2(unsigned long long a,
                                                    unsigned long long b,
                                                    unsigned long long c) {
    unsigned long long d;
    asm("fma.rn.f32x2 %0, %1, %2, %3;" : "=l"(d) : "l"(a), "l"(b), "l"(c));
    return d;
}

__global__ __launch_bounds__(NTHREADS, 2)
void moe_router_kernel(const float* __restrict__ X,
                       const float* __restrict__ W,
                       const float* __restrict__ BIAS,
                       float* __restrict__ OUTW,
                       float* __restrict__ OUTI,
                       int writeIdx, int Ntok)
{
    __shared__ SmemT sm;
    const int tid = threadIdx.x;
    const int bm0 = blockIdx.x * BM;

    // 4 tokens x 8 experts per thread (16 threads over tokens, 16 over experts)
    const int tm = (tid & 15) * 4;
    const int te = (tid >> 4) * 8;

    // x tile loads: 64 rows x 16 cols = 256 float4; 1 per thread
    const int ra = tid >> 2;
    const int ca = (tid & 3) * 4;
    // w tile loads: 128 rows x 16 cols = 512 float4; 2 per thread
    int re[2], ce[2];
#pragma unroll
    for (int p = 0; p < 2; ++p) {
        int q = tid + NTHREADS * p;
        re[p] = q >> 2;
        ce[p] = (q & 3) * 4;
    }

    float4 axr, bwr[2];
    {
        int row = bm0 + ra;
        axr = (row < Ntok)
            ? *reinterpret_cast<const float4*>(X + (size_t)row * D_MODEL + ca)
            : make_float4(0.f, 0.f, 0.f, 0.f);
#pragma unroll
        for (int p = 0; p < 2; ++p)
            bwr[p] = *reinterpret_cast<const float4*>(W + (size_t)re[p] * D_MODEL + ce[p]);
    }

    // accumulators: 4 tokens x 4 expert-pairs (f32x2 packed over adjacent experts)
    unsigned long long acc2[4][4];
#pragma unroll
    for (int i = 0; i < 4; ++i)
#pragma unroll
        for (int j = 0; j < 4; ++j)
            acc2[i][j] = 0ull;

    // stage prologue tile into buf 0 (As duplicated)
    {
        float v[4] = {axr.x, axr.y, axr.z, axr.w};
#pragma unroll
        for (int j = 0; j < 4; ++j)
            *reinterpret_cast<float2*>(&sm.g.As[0][ca + j][2 * ra]) = make_float2(v[j], v[j]);
#pragma unroll
        for (int p = 0; p < 2; ++p) {
            sm.g.Bs[0][ce[p] + 0][re[p]] = bwr[p].x;
            sm.g.Bs[0][ce[p] + 1][re[p]] = bwr[p].y;
            sm.g.Bs[0][ce[p] + 2][re[p]] = bwr[p].z;
            sm.g.Bs[0][ce[p] + 3][re[p]] = bwr[p].w;
        }
    }
    __syncthreads();

    const int NKT = D_MODEL / BK;   // 128
    int buf = 0;
    for (int kt = 0; kt < NKT; ++kt) {
        // prefetch next tile into registers
        if (kt + 1 < NKT) {
            const int k0 = (kt + 1) * BK;
            int row = bm0 + ra;
            axr = (row < Ntok)
                ? *reinterpret_cast<const float4*>(X + (size_t)row * D_MODEL + k0 + ca)
                : make_float4(0.f, 0.f, 0.f, 0.f);
#pragma unroll
            for (int p = 0; p < 2; ++p)
                bwr[p] = *reinterpret_cast<const float4*>(W + (size_t)re[p] * D_MODEL + k0 + ce[p]);
        }

        // compute BK k-steps: pure FFMA2, no packing MOVs
#pragma unroll
        for (int k = 0; k < BK; ++k) {
            ulonglong2 ad0 = *reinterpret_cast<const ulonglong2*>(&sm.g.As[buf][k][2 * tm]);      // {x_t0,x_t0},{x_t1,x_t1}
            ulonglong2 ad1 = *reinterpret_cast<const ulonglong2*>(&sm.g.As[buf][k][2 * tm + 4]);  // {x_t2,x_t2},{x_t3,x_t3}
            ulonglong2 b0  = *reinterpret_cast<const ulonglong2*>(&sm.g.Bs[buf][k][te]);          // {w_e0,w_e1},{w_e2,w_e3}
            ulonglong2 b1  = *reinterpret_cast<const ulonglong2*>(&sm.g.Bs[buf][k][te + 4]);
            unsigned long long av[4] = {ad0.x, ad0.y, ad1.x, ad1.y};
            unsigned long long bv[4] = {b0.x, b0.y, b1.x, b1.y};
#pragma unroll
            for (int mi = 0; mi < 4; ++mi)
#pragma unroll
                for (int nj = 0; nj < 4; ++nj)
                    acc2[mi][nj] = ffma2(av[mi], bv[nj], acc2[mi][nj]);
        }

        // stage prefetched tile into other buffer
        if (kt + 1 < NKT) {
            int nb = buf ^ 1;
            float v[4] = {axr.x, axr.y, axr.z, axr.w};
#pragma unroll
            for (int j = 0; j < 4; ++j)
                *reinterpret_cast<float2*>(&sm.g.As[nb][ca + j][2 * ra]) = make_float2(v[j], v[j]);
#pragma unroll
            for (int p = 0; p < 2; ++p) {
                sm.g.Bs[nb][ce[p] + 0][re[p]] = bwr[p].x;
                sm.g.Bs[nb][ce[p] + 1][re[p]] = bwr[p].y;
                sm.g.Bs[nb][ce[p] + 2][re[p]] = bwr[p].z;
                sm.g.Bs[nb][ce[p] + 3][re[p]] = bwr[p].w;
            }
            __syncthreads();
            buf = nb;
        }
    }

    // ---- write logits tile to smem (union reuse: sync first) ----
    __syncthreads();
#pragma unroll
    for (int mi = 0; mi < 4; ++mi) {
        float2 p0 = *reinterpret_cast<float2*>(&acc2[mi][0]);
        float2 p1 = *reinterpret_cast<float2*>(&acc2[mi][1]);
        float2 p2 = *reinterpret_cast<float2*>(&acc2[mi][2]);
        float2 p3 = *reinterpret_cast<float2*>(&acc2[mi][3]);
        *reinterpret_cast<float4*>(&sm.Ls[tm + mi][te])     = make_float4(p0.x, p0.y, p1.x, p1.y);
        *reinterpret_cast<float4*>(&sm.Ls[tm + mi][te + 4]) = make_float4(p2.x, p2.y, p3.x, p3.y);
    }
    __syncthreads();

    // ---- router epilogue: 1 warp per token ----
    const int lane = tid & 31;
    const int wrp  = tid >> 5;

    for (int t = wrp; t < BM; t += (NTHREADS / 32)) {
        int gt = bm0 + t;
        if (gt >= Ntok) continue;

        float v0 = sm.Ls[t][lane];
        float v1 = sm.Ls[t][lane + 32];
        float v2 = sm.Ls[t][lane + 64];
        float v3 = sm.Ls[t][lane + 96];

        // softmax over 128
        float mx = fmaxf(fmaxf(v0, v1), fmaxf(v2, v3));
#pragma unroll
        for (int off = 16; off > 0; off >>= 1)
            mx = fmaxf(mx, __shfl_xor_sync(0xffffffffu, mx, off));

        float e0 = expf(v0 - mx);
        float e1 = expf(v1 - mx);
        float e2 = expf(v2 - mx);
        float e3 = expf(v3 - mx);
        float sum = e0 + e1 + e2 + e3;
#pragma unroll
        for (int off = 16; off > 0; off >>= 1)
            sum += __shfl_xor_sync(0xffffffffu, sum, off);

        float s0 = e0 / sum, s1 = e1 / sum, s2 = e2 / sum, s3 = e3 / sum;

        // bias-adjusted scores for selection only
        float bb0 = s0 + __ldg(BIAS + lane);
        float bb1 = s1 + __ldg(BIAS + lane + 32);
        float bb2 = s2 + __ldg(BIAS + lane + 64);
        float bb3 = s3 + __ldg(BIAS + lane + 96);

        float topw[TOPK];
        int   topi[TOPK];

#pragma unroll
        for (int i = 0; i < TOPK; ++i) {
            float bv = bb0; int bi = lane;
            if (bb1 > bv) { bv = bb1; bi = lane + 32; }
            if (bb2 > bv) { bv = bb2; bi = lane + 64; }
            if (bb3 > bv) { bv = bb3; bi = lane + 96; }
#pragma unroll
            for (int off = 16; off > 0; off >>= 1) {
                float ov = __shfl_xor_sync(0xffffffffu, bv, off);
                int   oi = __shfl_xor_sync(0xffffffffu, bi, off);
                if (ov > bv || (ov == bv && oi < bi)) { bv = ov; bi = oi; }
            }
            topi[i] = bi;
            int src = bi & 31, slot = bi >> 5;
            float sv = (slot == 0) ? s0 : (slot == 1) ? s1 : (slot == 2) ? s2 : s3;
            sv = __shfl_sync(0xffffffffu, sv, src);
            topw[i] = sv;
            if (lane == src) {
                if      (slot == 0) bb0 = -INFINITY;
                else if (slot == 1) bb1 = -INFINITY;
                else if (slot == 2) bb2 = -INFINITY;
                else                bb3 = -INFINITY;
            }
        }

        float n2 = 0.f;
#pragma unroll
        for (int i = 0; i < TOPK; ++i) n2 += topw[i] * topw[i];
        float nrm = sqrtf(n2);

        if (lane == 0) {
            size_t base = (size_t)gt * TOPK;
            float4 w0 = make_float4(topw[0] / nrm, topw[1] / nrm, topw[2] / nrm, topw[3] / nrm);
            float4 w1 = make_float4(topw[4] / nrm, topw[5] / nrm, topw[6] / nrm, topw[7] / nrm);
            *reinterpret_cast<float4*>(&OUTW[base])     = w0;
            *reinterpret_cast<float4*>(&OUTW[base + 4]) = w1;
            if (writeIdx) {
                float4 i0 = make_float4((float)topi[0], (float)topi[1], (float)topi[2], (float)topi[3]);
                float4 i1 = make_float4((float)topi[4], (float)topi[5], (float)topi[6], (float)topi[7]);
                *reinterpret_cast<float4*>(&OUTI[base])     = i0;
                *reinterpret_cast<float4*>(&OUTI[base + 4]) = i1;
            }
        }
    }
}

extern "C" void kernel_launch(void* const* d_in, const int* in_sizes, int n_in,
                              void* d_out, int out_size)
{
    const float* x    = (const float*)d_in[0];   // (B*S, D) fp32
    const float* w    = (const float*)d_in[1];   // (E, D) fp32
    const float* bias = (const float*)d_in[2];   // (E,) fp32

    const int Ntok = in_sizes[0] / D_MODEL;      // 16384

    float* outw = (float*)d_out;
    int writeIdx = (out_size >= 2 * Ntok * TOPK) ? 1 : 0;
    float* outi = outw + (size_t)Ntok * TOPK;

    int grid = (Ntok + BM - 1) / BM;
    moe_router_kernel<<<grid, NTHREADS>>>(x, w, bias, outw, outi, writeIdx, Ntok);
}

// round 6
// speedup vs baseline: 2.2084x; 2.2084x over previous
#include <cuda_runtime.h>
#include <math.h>
#include <stdint.h>

#define D_MODEL 2048
#define NEXP    128
#define BM      128
#define KC      32
#define NKC     (D_MODEL / KC)    // 64
#define NTHREADS 256
#define TOPK    8

#define SAW    36                  // smem row stride in floats (conflict-free: 36 mod 32 = 4)
#define TILEF  (128 * SAW)         // floats per precision tile (4608)
#define BUFF   (4 * TILEF)         // floats per buffer: A_hi, A_lo, B_hi, B_lo
#define SMEM_REQ (2 * BUFF * 4)    // 147456 bytes
#define LS_W   132

__device__ __forceinline__ float tf32_rna(float x) {
    uint32_t u;
    asm("cvt.rna.tf32.f32 %0, %1;" : "=r"(u) : "f"(x));
    return __uint_as_float(u);
}
__device__ __forceinline__ void split(float x, float& h, float& l) {
    h = tf32_rna(x);
    l = tf32_rna(x - h);
}

__device__ __forceinline__ void mma_tf32(float* d, const float* a, float b0, float b1) {
    asm volatile(
        "mma.sync.aligned.m16n8k8.row.col.f32.tf32.tf32.f32 "
        "{%0,%1,%2,%3}, {%4,%5,%6,%7}, {%8,%9}, {%0,%1,%2,%3};"
        : "+f"(d[0]), "+f"(d[1]), "+f"(d[2]), "+f"(d[3])
        : "r"(__float_as_uint(a[0])), "r"(__float_as_uint(a[1])),
          "r"(__float_as_uint(a[2])), "r"(__float_as_uint(a[3])),
          "r"(__float_as_uint(b0)), "r"(__float_as_uint(b1)));
}

__global__ __launch_bounds__(NTHREADS, 1)
void moe_router_kernel(const float* __restrict__ X,
                       const float* __restrict__ W,
                       const float* __restrict__ BIAS,
                       float* __restrict__ OUTW,
                       float* __restrict__ OUTI,
                       int writeIdx, int Ntok)
{
    extern __shared__ float Sm[];

    const int tid  = threadIdx.x;
    const int wid  = tid >> 5;
    const int lane = tid & 31;
    const int bm0  = blockIdx.x * BM;

    const int wm = wid >> 1;        // token group: wm*32
    const int wn = wid & 1;         // expert group: wn*64

    // global load mapping: per operand per chunk: 128 rows x 8 float4; 4/thread
    int rA[4], cA[4];
#pragma unroll
    for (int p = 0; p < 4; ++p) {
        int idx = tid + p * NTHREADS;
        rA[p] = idx >> 3;
        cA[p] = (idx & 7) * 4;
    }

    float acc[2][8][4];
#pragma unroll
    for (int i = 0; i < 2; ++i)
#pragma unroll
        for (int j = 0; j < 8; ++j)
#pragma unroll
            for (int q = 0; q < 4; ++q)
                acc[i][j][q] = 0.f;

    float4 axr[4], bwr[4];
    // prologue: load chunk 0
#pragma unroll
    for (int p = 0; p < 4; ++p) {
        int row = bm0 + rA[p];
        axr[p] = (row < Ntok)
            ? *reinterpret_cast<const float4*>(X + (size_t)row * D_MODEL + cA[p])
            : make_float4(0.f, 0.f, 0.f, 0.f);
        bwr[p] = *reinterpret_cast<const float4*>(W + (size_t)rA[p] * D_MODEL + cA[p]);
    }

    // store chunk 0 into buf 0 (split tf32 hi/lo)
    {
        float* AH = Sm;
        float* AL = Sm + TILEF;
        float* BH = Sm + 2 * TILEF;
        float* BL = Sm + 3 * TILEF;
#pragma unroll
        for (int p = 0; p < 4; ++p) {
            int off = rA[p] * SAW + cA[p];
            float4 h4, l4;
            split(axr[p].x, h4.x, l4.x); split(axr[p].y, h4.y, l4.y);
            split(axr[p].z, h4.z, l4.z); split(axr[p].w, h4.w, l4.w);
            *reinterpret_cast<float4*>(AH + off) = h4;
            *reinterpret_cast<float4*>(AL + off) = l4;
            split(bwr[p].x, h4.x, l4.x); split(bwr[p].y, h4.y, l4.y);
            split(bwr[p].z, h4.z, l4.z); split(bwr[p].w, h4.w, l4.w);
            *reinterpret_cast<float4*>(BH + off) = h4;
            *reinterpret_cast<float4*>(BL + off) = l4;
        }
    }
    __syncthreads();

    const int alanebase = (wm * 32 + (lane >> 2)) * SAW + (lane & 3);
    const int blanebase = (wn * 64 + (lane >> 2)) * SAW + (lane & 3);

    for (int c = 0; c < NKC; ++c) {
        const int buf = c & 1;
        // prefetch next chunk into registers
        if (c + 1 < NKC) {
            const int k0 = (c + 1) * KC;
#pragma unroll
            for (int p = 0; p < 4; ++p) {
                int row = bm0 + rA[p];
                axr[p] = (row < Ntok)
                    ? *reinterpret_cast<const float4*>(X + (size_t)row * D_MODEL + k0 + cA[p])
                    : make_float4(0.f, 0.f, 0.f, 0.f);
                bwr[p] = *reinterpret_cast<const float4*>(W + (size_t)rA[p] * D_MODEL + k0 + cA[p]);
            }
        }

        // ---- compute chunk c: 4 k8-steps ----
        const float* sb = Sm + buf * BUFF;
        const float* AH = sb;
        const float* AL = sb + TILEF;
        const float* BH = sb + 2 * TILEF;
        const float* BL = sb + 3 * TILEF;
#pragma unroll
        for (int ks = 0; ks < KC / 8; ++ks) {
            const int kb = ks * 8;
            float aH[2][4], aL[2][4];
#pragma unroll
            for (int mt = 0; mt < 2; ++mt) {
                int b0 = alanebase + mt * 16 * SAW + kb;
                aH[mt][0] = AH[b0];
                aH[mt][1] = AH[b0 + 8 * SAW];
                aH[mt][2] = AH[b0 + 4];
                aH[mt][3] = AH[b0 + 8 * SAW + 4];
                aL[mt][0] = AL[b0];
                aL[mt][1] = AL[b0 + 8 * SAW];
                aL[mt][2] = AL[b0 + 4];
                aL[mt][3] = AL[b0 + 8 * SAW + 4];
            }
#pragma unroll
            for (int ng = 0; ng < 8; ++ng) {
                int bb = blanebase + ng * 8 * SAW + kb;
                float bh0 = BH[bb], bh1 = BH[bb + 4];
                float bl0 = BL[bb], bl1 = BL[bb + 4];
#pragma unroll
                for (int mt = 0; mt < 2; ++mt) {
                    mma_tf32(acc[mt][ng], aL[mt], bh0, bh1);   // lo*hi
                    mma_tf32(acc[mt][ng], aH[mt], bl0, bl1);   // hi*lo
                    mma_tf32(acc[mt][ng], aH[mt], bh0, bh1);   // hi*hi
                }
            }
        }

        // stage prefetched chunk into the other buffer
        if (c + 1 < NKC) {
            float* db = Sm + ((c + 1) & 1) * BUFF;
            float* nAH = db;
            float* nAL = db + TILEF;
            float* nBH = db + 2 * TILEF;
            float* nBL = db + 3 * TILEF;
            __syncthreads();   // everyone done reading buf^1 from 2 chunks ago? (buf^1 == (c+1)&1; last read at chunk c-1) -> safe
#pragma unroll
            for (int p = 0; p < 4; ++p) {
                int off = rA[p] * SAW + cA[p];
                float4 h4, l4;
                split(axr[p].x, h4.x, l4.x); split(axr[p].y, h4.y, l4.y);
                split(axr[p].z, h4.z, l4.z); split(axr[p].w, h4.w, l4.w);
                *reinterpret_cast<float4*>(nAH + off) = h4;
                *reinterpret_cast<float4*>(nAL + off) = l4;
                split(bwr[p].x, h4.x, l4.x); split(bwr[p].y, h4.y, l4.y);
                split(bwr[p].z, h4.z, l4.z); split(bwr[p].w, h4.w, l4.w);
                *reinterpret_cast<float4*>(nBH + off) = h4;
                *reinterpret_cast<float4*>(nBL + off) = l4;
            }
            __syncthreads();
        }
    }

    // ---- logits to smem ----
    __syncthreads();
    float* Ls = Sm;
    {
        const int g  = lane >> 2;
        const int t2 = (lane & 3) * 2;
#pragma unroll
        for (int mt = 0; mt < 2; ++mt) {
            int row = wm * 32 + mt * 16 + g;
#pragma unroll
            for (int ng = 0; ng < 8; ++ng) {
                int col = wn * 64 + ng * 8 + t2;
                *reinterpret_cast<float2*>(&Ls[row * LS_W + col]) =
                    make_float2(acc[mt][ng][0], acc[mt][ng][1]);
                *reinterpret_cast<float2*>(&Ls[(row + 8) * LS_W + col]) =
                    make_float2(acc[mt][ng][2], acc[mt][ng][3]);
            }
        }
    }
    __syncthreads();

    // ---- router epilogue: 1 warp per token ----
    for (int t = wid; t < BM; t += (NTHREADS / 32)) {
        int gt = bm0 + t;
        if (gt >= Ntok) continue;
        const float* Lr = Ls + t * LS_W;

        float v0 = Lr[lane];
        float v1 = Lr[lane + 32];
        float v2 = Lr[lane + 64];
        float v3 = Lr[lane + 96];

        float mx = fmaxf(fmaxf(v0, v1), fmaxf(v2, v3));
#pragma unroll
        for (int off = 16; off > 0; off >>= 1)
            mx = fmaxf(mx, __shfl_xor_sync(0xffffffffu, mx, off));

        float e0 = expf(v0 - mx);
        float e1 = expf(v1 - mx);
        float e2 = expf(v2 - mx);
        float e3 = expf(v3 - mx);
        float sum = e0 + e1 + e2 + e3;
#pragma unroll
        for (int off = 16; off > 0; off >>= 1)
            sum += __shfl_xor_sync(0xffffffffu, sum, off);

        float s0 = e0 / sum, s1 = e1 / sum, s2 = e2 / sum, s3 = e3 / sum;

        float bb0 = s0 + __ldg(BIAS + lane);
        float bb1 = s1 + __ldg(BIAS + lane + 32);
        float bb2 = s2 + __ldg(BIAS + lane + 64);
        float bb3 = s3 + __ldg(BIAS + lane + 96);

        float topw[TOPK];
        int   topi[TOPK];
#pragma unroll
        for (int i = 0; i < TOPK; ++i) {
            float bv = bb0; int bi = lane;
            if (bb1 > bv) { bv = bb1; bi = lane + 32; }
            if (bb2 > bv) { bv = bb2; bi = lane + 64; }
            if (bb3 > bv) { bv = bb3; bi = lane + 96; }
#pragma unroll
            for (int off = 16; off > 0; off >>= 1) {
                float ov = __shfl_xor_sync(0xffffffffu, bv, off);
                int   oi = __shfl_xor_sync(0xffffffffu, bi, off);
                if (ov > bv || (ov == bv && oi < bi)) { bv = ov; bi = oi; }
            }
            topi[i] = bi;
            int src = bi & 31, slot = bi >> 5;
            float sv = (slot == 0) ? s0 : (slot == 1) ? s1 : (slot == 2) ? s2 : s3;
            sv = __shfl_sync(0xffffffffu, sv, src);
            topw[i] = sv;
            if (lane == src) {
                if      (slot == 0) bb0 = -INFINITY;
                else if (slot == 1) bb1 = -INFINITY;
                else if (slot == 2) bb2 = -INFINITY;
                else                bb3 = -INFINITY;
            }
        }

        float n2 = 0.f;
#pragma unroll
        for (int i = 0; i < TOPK; ++i) n2 += topw[i] * topw[i];
        float nrm = sqrtf(n2);

        if (lane == 0) {
            size_t base = (size_t)gt * TOPK;
            float4 w0 = make_float4(topw[0] / nrm, topw[1] / nrm, topw[2] / nrm, topw[3] / nrm);
            float4 w1 = make_float4(topw[4] / nrm, topw[5] / nrm, topw[6] / nrm, topw[7] / nrm);
            *reinterpret_cast<float4*>(&OUTW[base])     = w0;
            *reinterpret_cast<float4*>(&OUTW[base + 4]) = w1;
            if (writeIdx) {
                float4 i0 = make_float4((float)topi[0], (float)topi[1], (float)topi[2], (float)topi[3]);
                float4 i1 = make_float4((float)topi[4], (float)topi[5], (float)topi[6], (float)topi[7]);
                *reinterpret_cast<float4*>(&OUTI[base])     = i0;
                *reinterpret_cast<float4*>(&OUTI[base + 4]) = i1;
            }
        }
    }
}

extern "C" void kernel_launch(void* const* d_in, const int* in_sizes, int n_in,
                              void* d_out, int out_size)
{
    const float* x    = (const float*)d_in[0];
    const float* w    = (const float*)d_in[1];
    const float* bias = (const float*)d_in[2];

    const int Ntok = in_sizes[0] / D_MODEL;

    float* outw = (float*)d_out;
    int writeIdx = (out_size >= 2 * Ntok * TOPK) ? 1 : 0;
    float* outi = outw + (size_t)Ntok * TOPK;

    cudaFuncSetAttribute(moe_router_kernel,
                         cudaFuncAttributeMaxDynamicSharedMemorySize, SMEM_REQ);

    int grid = (Ntok + BM - 1) / BM;
    moe_router_kernel<<<grid, NTHREADS, SMEM_REQ>>>(x, w, bias, outw, outi, writeIdx, Ntok);
}

// round 7
// speedup vs baseline: 2.3261x; 1.0533x over previous
#include <cuda_runtime.h>
#include <math.h>
#include <stdint.h>

#define D_MODEL 2048
#define NEXP    128
#define BM      128
#define KC      32
#define NKC     (D_MODEL / KC)    // 64
#define NTHREADS 512
#define TOPK    8

#define SAW    36                  // smem row stride in floats (conflict-free)
#define TILEF  (128 * SAW)         // floats per precision tile
#define BUFF   (4 * TILEF)         // A_hi, A_lo, B_hi, B_lo
#define SMEM_REQ (2 * BUFF * 4)    // 147456 bytes
#define LS_W   132

__device__ __forceinline__ float tf32_rna(float x) {
    uint32_t u;
    asm("cvt.rna.tf32.f32 %0, %1;" : "=r"(u) : "f"(x));
    return __uint_as_float(u);
}
__device__ __forceinline__ void split(float x, float& h, float& l) {
    h = tf32_rna(x);
    l = tf32_rna(x - h);
}

__device__ __forceinline__ void mma_tf32(float* d, const float* a, float b0, float b1) {
    asm volatile(
        "mma.sync.aligned.m16n8k8.row.col.f32.tf32.tf32.f32 "
        "{%0,%1,%2,%3}, {%4,%5,%6,%7}, {%8,%9}, {%0,%1,%2,%3};"
        : "+f"(d[0]), "+f"(d[1]), "+f"(d[2]), "+f"(d[3])
        : "r"(__float_as_uint(a[0])), "r"(__float_as_uint(a[1])),
          "r"(__float_as_uint(a[2])), "r"(__float_as_uint(a[3])),
          "r"(__float_as_uint(b0)), "r"(__float_as_uint(b1)));
}

__global__ __launch_bounds__(NTHREADS, 1)
void moe_router_kernel(const float* __restrict__ X,
                       const float* __restrict__ W,
                       const float* __restrict__ BIAS,
                       float* __restrict__ OUTW,
                       float* __restrict__ OUTI,
                       int writeIdx, int Ntok)
{
    extern __shared__ float Sm[];

    const int tid  = threadIdx.x;
    const int wid  = tid >> 5;
    const int lane = tid & 31;
    const int bm0  = blockIdx.x * BM;

    const int wm = wid >> 2;        // 0..3 -> token base wm*32
    const int wn = wid & 3;         // 0..3 -> expert base wn*32

    // global loads: per operand per chunk 1024 float4; 2 per thread
    int rA[2], cA[2];
#pragma unroll
    for (int p = 0; p < 2; ++p) {
        int idx = tid + p * NTHREADS;
        rA[p] = idx >> 3;
        cA[p] = (idx & 7) * 4;
    }

    float acc[2][4][4];
#pragma unroll
    for (int i = 0; i < 2; ++i)
#pragma unroll
        for (int j = 0; j < 4; ++j)
#pragma unroll
            for (int q = 0; q < 4; ++q)
                acc[i][j][q] = 0.f;

    float4 axr[2], bwr[2];
#pragma unroll
    for (int p = 0; p < 2; ++p) {
        int row = bm0 + rA[p];
        axr[p] = (row < Ntok)
            ? *reinterpret_cast<const float4*>(X + (size_t)row * D_MODEL + cA[p])
            : make_float4(0.f, 0.f, 0.f, 0.f);
        bwr[p] = *reinterpret_cast<const float4*>(W + (size_t)rA[p] * D_MODEL + cA[p]);
    }

    // store chunk 0 into buf 0
    {
        float* AH = Sm;
        float* AL = Sm + TILEF;
        float* BH = Sm + 2 * TILEF;
        float* BL = Sm + 3 * TILEF;
#pragma unroll
        for (int p = 0; p < 2; ++p) {
            int off = rA[p] * SAW + cA[p];
            float4 h4, l4;
            split(axr[p].x, h4.x, l4.x); split(axr[p].y, h4.y, l4.y);
            split(axr[p].z, h4.z, l4.z); split(axr[p].w, h4.w, l4.w);
            *reinterpret_cast<float4*>(AH + off) = h4;
            *reinterpret_cast<float4*>(AL + off) = l4;
            split(bwr[p].x, h4.x, l4.x); split(bwr[p].y, h4.y, l4.y);
            split(bwr[p].z, h4.z, l4.z); split(bwr[p].w, h4.w, l4.w);
            *reinterpret_cast<float4*>(BH + off) = h4;
            *reinterpret_cast<float4*>(BL + off) = l4;
        }
    }
    __syncthreads();

    const int alanebase = (wm * 32 + (lane >> 2)) * SAW + (lane & 3);
    const int blanebase = (wn * 32 + (lane >> 2)) * SAW + (lane & 3);

    for (int c = 0; c < NKC; ++c) {
        const int buf = c & 1;
        if (c + 1 < NKC) {
            const int k0 = (c + 1) * KC;
#pragma unroll
            for (int p = 0; p < 2; ++p) {
                int row = bm0 + rA[p];
                axr[p] = (row < Ntok)
                    ? *reinterpret_cast<const float4*>(X + (size_t)row * D_MODEL + k0 + cA[p])
                    : make_float4(0.f, 0.f, 0.f, 0.f);
                bwr[p] = *reinterpret_cast<const float4*>(W + (size_t)rA[p] * D_MODEL + k0 + cA[p]);
            }
        }

        const float* sb = Sm + buf * BUFF;
        const float* AH = sb;
        const float* AL = sb + TILEF;
        const float* BH = sb + 2 * TILEF;
        const float* BL = sb + 3 * TILEF;
#pragma unroll
        for (int ks = 0; ks < KC / 8; ++ks) {
            const int kb = ks * 8;
            float aH[2][4], aL[2][4];
#pragma unroll
            for (int mt = 0; mt < 2; ++mt) {
                int b0 = alanebase + mt * 16 * SAW + kb;
                aH[mt][0] = AH[b0];
                aH[mt][1] = AH[b0 + 8 * SAW];
                aH[mt][2] = AH[b0 + 4];
                aH[mt][3] = AH[b0 + 8 * SAW + 4];
                aL[mt][0] = AL[b0];
                aL[mt][1] = AL[b0 + 8 * SAW];
                aL[mt][2] = AL[b0 + 4];
                aL[mt][3] = AL[b0 + 8 * SAW + 4];
            }
#pragma unroll
            for (int ng = 0; ng < 4; ++ng) {
                int bb = blanebase + ng * 8 * SAW + kb;
                float bh0 = BH[bb], bh1 = BH[bb + 4];
                float bl0 = BL[bb], bl1 = BL[bb + 4];
#pragma unroll
                for (int mt = 0; mt < 2; ++mt) {
                    mma_tf32(acc[mt][ng], aL[mt], bh0, bh1);   // lo*hi
                    mma_tf32(acc[mt][ng], aH[mt], bl0, bl1);   // hi*lo
                    mma_tf32(acc[mt][ng], aH[mt], bh0, bh1);   // hi*hi
                }
            }
        }

        if (c + 1 < NKC) {
            float* db = Sm + ((c + 1) & 1) * BUFF;
            float* nAH = db;
            float* nAL = db + TILEF;
            float* nBH = db + 2 * TILEF;
            float* nBL = db + 3 * TILEF;
            __syncthreads();
#pragma unroll
            for (int p = 0; p < 2; ++p) {
                int off = rA[p] * SAW + cA[p];
                float4 h4, l4;
                split(axr[p].x, h4.x, l4.x); split(axr[p].y, h4.y, l4.y);
                split(axr[p].z, h4.z, l4.z); split(axr[p].w, h4.w, l4.w);
                *reinterpret_cast<float4*>(nAH + off) = h4;
                *reinterpret_cast<float4*>(nAL + off) = l4;
                split(bwr[p].x, h4.x, l4.x); split(bwr[p].y, h4.y, l4.y);
                split(bwr[p].z, h4.z, l4.z); split(bwr[p].w, h4.w, l4.w);
                *reinterpret_cast<float4*>(nBH + off) = h4;
                *reinterpret_cast<float4*>(nBL + off) = l4;
            }
            __syncthreads();
        }
    }

    // ---- logits to smem ----
    __syncthreads();
    float* Ls = Sm;
    {
        const int g  = lane >> 2;
        const int t2 = (lane & 3) * 2;
#pragma unroll
        for (int mt = 0; mt < 2; ++mt) {
            int row = wm * 32 + mt * 16 + g;
#pragma unroll
            for (int ng = 0; ng < 4; ++ng) {
                int col = wn * 32 + ng * 8 + t2;
                *reinterpret_cast<float2*>(&Ls[row * LS_W + col]) =
                    make_float2(acc[mt][ng][0], acc[mt][ng][1]);
                *reinterpret_cast<float2*>(&Ls[(row + 8) * LS_W + col]) =
                    make_float2(acc[mt][ng][2], acc[mt][ng][3]);
            }
        }
    }
    __syncthreads();

    // ---- router epilogue: 1 warp per token ----
    for (int t = wid; t < BM; t += (NTHREADS / 32)) {
        int gt = bm0 + t;
        if (gt >= Ntok) continue;
        const float* Lr = Ls + t * LS_W;

        float v0 = Lr[lane];
        float v1 = Lr[lane + 32];
        float v2 = Lr[lane + 64];
        float v3 = Lr[lane + 96];

        float mx = fmaxf(fmaxf(v0, v1), fmaxf(v2, v3));
#pragma unroll
        for (int off = 16; off > 0; off >>= 1)
            mx = fmaxf(mx, __shfl_xor_sync(0xffffffffu, mx, off));

        float e0 = expf(v0 - mx);
        float e1 = expf(v1 - mx);
        float e2 = expf(v2 - mx);
        float e3 = expf(v3 - mx);
        float sum = e0 + e1 + e2 + e3;
#pragma unroll
        for (int off = 16; off > 0; off >>= 1)
            sum += __shfl_xor_sync(0xffffffffu, sum, off);

        float s0 = e0 / sum, s1 = e1 / sum, s2 = e2 / sum, s3 = e3 / sum;

        float bb0 = s0 + __ldg(BIAS + lane);
        float bb1 = s1 + __ldg(BIAS + lane + 32);
        float bb2 = s2 + __ldg(BIAS + lane + 64);
        float bb3 = s3 + __ldg(BIAS + lane + 96);

        float topw[TOPK];
        int   topi[TOPK];
#pragma unroll
        for (int i = 0; i < TOPK; ++i) {
            float bv = bb0; int bi = lane;
            if (bb1 > bv) { bv = bb1; bi = lane + 32; }
            if (bb2 > bv) { bv = bb2; bi = lane + 64; }
            if (bb3 > bv) { bv = bb3; bi = lane + 96; }
#pragma unroll
            for (int off = 16; off > 0; off >>= 1) {
                float ov = __shfl_xor_sync(0xffffffffu, bv, off);
                int   oi = __shfl_xor_sync(0xffffffffu, bi, off);
                if (ov > bv || (ov == bv && oi < bi)) { bv = ov; bi = oi; }
            }
            topi[i] = bi;
            int src = bi & 31, slot = bi >> 5;
            float sv = (slot == 0) ? s0 : (slot == 1) ? s1 : (slot == 2) ? s2 : s3;
            sv = __shfl_sync(0xffffffffu, sv, src);
            topw[i] = sv;
            if (lane == src) {
                if      (slot == 0) bb0 = -INFINITY;
                else if (slot == 1) bb1 = -INFINITY;
                else if (slot == 2) bb2 = -INFINITY;
                else                bb3 = -INFINITY;
            }
        }

        float n2 = 0.f;
#pragma unroll
        for (int i = 0; i < TOPK; ++i) n2 += topw[i] * topw[i];
        float nrm = sqrtf(n2);

        if (lane == 0) {
            size_t base = (size_t)gt * TOPK;
            float4 w0 = make_float4(topw[0] / nrm, topw[1] / nrm, topw[2] / nrm, topw[3] / nrm);
            float4 w1 = make_float4(topw[4] / nrm, topw[5] / nrm, topw[6] / nrm, topw[7] / nrm);
            *reinterpret_cast<float4*>(&OUTW[base])     = w0;
            *reinterpret_cast<float4*>(&OUTW[base + 4]) = w1;
            if (writeIdx) {
                float4 i0 = make_float4((float)topi[0], (float)topi[1], (float)topi[2], (float)topi[3]);
                float4 i1 = make_float4((float)topi[4], (float)topi[5], (float)topi[6], (float)topi[7]);
                *reinterpret_cast<float4*>(&OUTI[base])     = i0;
                *reinterpret_cast<float4*>(&OUTI[base + 4]) = i1;
            }
        }
    }
}

extern "C" void kernel_launch(void* const* d_in, const int* in_sizes, int n_in,
                              void* d_out, int out_size)
{
    const float* x    = (const float*)d_in[0];
    const float* w    = (const float*)d_in[1];
    const float* bias = (const float*)d_in[2];

    const int Ntok = in_sizes[0] / D_MODEL;

    float* outw = (float*)d_out;
    int writeIdx = (out_size >= 2 * Ntok * TOPK) ? 1 : 0;
    float* outi = outw + (size_t)Ntok * TOPK;

    cudaFuncSetAttribute(moe_router_kernel,
                         cudaFuncAttributeMaxDynamicSharedMemorySize, SMEM_REQ);

    int grid = (Ntok + BM - 1) / BM;
    moe_router_kernel<<<grid, NTHREADS, SMEM_REQ>>>(x, w, bias, outw, outi, writeIdx, Ntok);
}